// round 15
// baseline (speedup 1.0000x reference)
#include <cuda_runtime.h>
#include <cuda_bf16.h>
#include <mma.h>
#include <cstdint>

using namespace nvcuda;

#define HH 128
#define WW 128
#define BB 4
#define CC 128
#define GG 2
#define CG 64
#define KIN 576   // 9*64
#define FG 64
#define NPIX (BB*HH*WW)   // 65536

// ---------------- offset conv v4 smem config (half channels) ----------------
#define XSTR 533
#define XS2_FLOATS (32 * XSTR)           // 17056
#define SW2_FLOATS (9 * 32 * 20)         // 5760
#define OFFC2_SMEM ((XS2_FLOATS + SW2_FLOATS) * 4)  // 91264 bytes -> 2 CTAs/SM

// ---------------- scratch globals ----------------
__device__ float g_off_buf [(size_t)GG * NPIX * 18];           // partial: ci 0..31
__device__ float g_off_buf2[(size_t)GG * NPIX * 18];           // partial: ci 32..63
__device__ float g_samp_buf[(size_t)GG * NPIX * KIN];          // 302MB
__device__ __nv_bfloat16 g_pwh[(size_t)GG * FG * KIN];         // pw hi, [g][f][kin]
__device__ __nv_bfloat16 g_pwl[(size_t)GG * FG * KIN];         // pw lo

// ---------------------------------------------------------------------------
// Kernel A v4: offset conv, split by ci-half across blocks (2 CTAs/SM).
// Block = (g, b, row-pair, ci-half). Writes partial sums; sample adds them.
// ---------------------------------------------------------------------------
__global__ void __launch_bounds__(256) offset_conv_v4(
        const float* __restrict__ x,
        const float* __restrict__ off_w,
        const float* __restrict__ off_b) {
    extern __shared__ float sm[];
    float* Xs = sm;                   // [32][XSTR]: rows r=0..3 at r*133, col px+1
    float* sw = sm + XS2_FLOATS;      // [9*32][20]

    int bid  = blockIdx.x;            // g*512 + b*128 + ypair*2 + ch
    int g    = bid >> 9;
    int rem  = bid & 511;
    int b    = rem >> 7;
    int rem2 = rem & 127;
    int y0   = (rem2 >> 1) << 1;
    int ch   = rem2 & 1;              // ci-half
    int tid  = threadIdx.x;           // 256

    // ---- stage this half's weights, padded to 20 floats per (j,ci') ----
    const float* wsrc = off_w + (size_t)g * 10368;
    for (int i = tid; i < 9 * 32 * 18; i += 256) {
        int oc  = i % 18;
        int t   = i / 18;             // j*32 + ci'
        int j   = t >> 5;
        int cip = t & 31;
        sw[t * 20 + oc] = wsrc[(size_t)(j * 64 + ch * 32 + cip) * 18 + oc];
    }

    // ---- zero halo columns ----
    for (int i = tid; i < 32 * 4 * 2; i += 256) {
        int ci   = i >> 3;
        int r    = (i >> 1) & 3;
        int cpos = (i & 1) ? 129 : 0;
        Xs[ci * XSTR + r * 133 + cpos] = 0.f;
    }
    // ---- zero out-of-image rows ----
    if (y0 == 0) {
        for (int i = tid; i < 32 * 130; i += 256)
            Xs[(i / 130) * XSTR + (i % 130)] = 0.f;
    }
    if (y0 == HH - 2) {
        for (int i = tid; i < 32 * 130; i += 256)
            Xs[(i / 130) * XSTR + 3 * 133 + (i % 130)] = 0.f;
    }

    // ---- stage x rows y0-1..y0+2, this ci-half, transposed channel-major ----
    for (int i = tid; i < 4 * 128 * 8; i += 256) {
        int c4 = i & 7;
        int t  = i >> 3;
        int px = t & 127;
        int r  = t >> 7;
        int yy = y0 - 1 + r;
        if (yy < 0 || yy >= HH) continue;
        const float4 v = *(const float4*)(x +
            (((size_t)(b * HH + yy) * WW + px) * CC + g * CG + ch * 32 + c4 * 4));
        int base = r * 133 + px + 1;
        Xs[(c4 * 4 + 0) * XSTR + base] = v.x;
        Xs[(c4 * 4 + 1) * XSTR + base] = v.y;
        Xs[(c4 * 4 + 2) * XSTR + base] = v.z;
        Xs[(c4 * 4 + 3) * XSTR + base] = v.w;
    }
    __syncthreads();

    int px   = tid & 127;
    int rsel = tid >> 7;
    float acc[18];
#pragma unroll
    for (int oc = 0; oc < 18; oc++)
        acc[oc] = ch ? 0.f : off_b[g * 18 + oc];

    for (int ci = 0; ci < 32; ci++) {
        const float* xp = Xs + ci * XSTR + rsel * 133 + px;
        float xv[3][3];
#pragma unroll
        for (int r = 0; r < 3; r++)
#pragma unroll
            for (int k = 0; k < 3; k++)
                xv[r][k] = xp[r * 133 + k];

        const float* wbase = sw + ci * 20;
#pragma unroll
        for (int ky = 0; ky < 3; ky++) {
#pragma unroll
            for (int kx = 0; kx < 3; kx++) {
                const float* w = wbase + (ky * 3 + kx) * (32 * 20);
                float4 w0 = *(const float4*)(w);
                float4 w1 = *(const float4*)(w + 4);
                float4 w2 = *(const float4*)(w + 8);
                float4 w3 = *(const float4*)(w + 12);
                float2 w4 = *(const float2*)(w + 16);
                float a = xv[ky][kx];
                float wv[18] = {w0.x,w0.y,w0.z,w0.w, w1.x,w1.y,w1.z,w1.w,
                                w2.x,w2.y,w2.z,w2.w, w3.x,w3.y,w3.z,w3.w,
                                w4.x,w4.y};
#pragma unroll
                for (int oc = 0; oc < 18; oc++) acc[oc] += a * wv[oc];
            }
        }
    }

    int m = (b * HH + y0 + rsel) * WW + px;
    float* op = (ch ? g_off_buf2 : g_off_buf) + ((size_t)g * NPIX + m) * 18;
#pragma unroll
    for (int oc = 0; oc < 18; oc++) op[oc] = acc[oc];
}

// ---------------------------------------------------------------------------
// Kernel B: bilinear sampling; offsets = sum of the two partial buffers.
// ---------------------------------------------------------------------------
__global__ void sample_kernel(const float* __restrict__ x) {
    int wid  = (blockIdx.x * blockDim.x + threadIdx.x) >> 5;
    int lane = threadIdx.x & 31;
    int k = wid % 9;
    int t = wid / 9;
    int m = t & (NPIX - 1);
    int g = t >> 16;

    int b    = m >> 14;
    int y    = (m >> 7) & 127;
    int xpix = m & 127;

    size_t ooff = ((size_t)g * NPIX + m) * 18 + 2 * k;
    float ox = g_off_buf[ooff]     + g_off_buf2[ooff];
    float oy = g_off_buf[ooff + 1] + g_off_buf2[ooff + 1];

    float fx = (float)xpix + (float)(k % 3 - 1) + ox;
    float fy = (float)y    + (float)(k / 3 - 1) + oy;
    fx = fminf(fmaxf(fx, 0.f), (float)(WW - 1));
    fy = fminf(fmaxf(fy, 0.f), (float)(HH - 1));

    float x0f = floorf(fx), y0f = floorf(fy);
    float x1f = fminf(x0f + 1.f, (float)(WW - 1));
    float y1f = fminf(y0f + 1.f, (float)(HH - 1));

    float tx  = fx - x0f, ty  = fy - y0f;
    float txc = x1f - fx, tyc = y1f - fy;
    float wa = txc * tyc;
    float wb = txc * ty;
    float wc = tx  * tyc;
    float wd = tx  * ty;

    int x0 = (int)x0f, x1 = (int)x1f, y0 = (int)y0f, y1 = (int)y1f;

    const float* base = x + (size_t)b * HH * WW * CC + g * CG;
    const float2* p00 = (const float2*)(base + ((size_t)y0 * WW + x0) * CC) + lane;
    const float2* p10 = (const float2*)(base + ((size_t)y1 * WW + x0) * CC) + lane;
    const float2* p01 = (const float2*)(base + ((size_t)y0 * WW + x1) * CC) + lane;
    const float2* p11 = (const float2*)(base + ((size_t)y1 * WW + x1) * CC) + lane;

    float2 a = __ldg(p00), bb2 = __ldg(p10), c2 = __ldg(p01), d2 = __ldg(p11);
    float2 v;
    v.x = wa * a.x + wb * bb2.x + wc * c2.x + wd * d2.x;
    v.y = wa * a.y + wb * bb2.y + wc * c2.y + wd * d2.y;

    float2* sp = (float2*)(g_samp_buf + ((size_t)g * NPIX + m) * KIN + k * CG) + lane;
    *sp = v;
}

// ---------------------------------------------------------------------------
// Prep: split pw weights into bf16 hi/lo, transposed to [g][f][kin].
// ---------------------------------------------------------------------------
__global__ void pw_split_kernel(const float* __restrict__ pw_w) {
    int idx = blockIdx.x * blockDim.x + threadIdx.x;
    if (idx >= GG * KIN * FG) return;
    int f   = idx & 63;
    int kin = (idx >> 6) % KIN;
    int g   = idx / (KIN * FG);
    float v = pw_w[idx];
    __nv_bfloat16 hi = __float2bfloat16(v);
    __nv_bfloat16 lo = __float2bfloat16(v - __bfloat162float(hi));
    size_t o = ((size_t)g * FG + f) * KIN + kin;
    g_pwh[o] = hi;
    g_pwl[o] = lo;
}

__device__ __forceinline__ uint32_t pack_bf2(__nv_bfloat16 a, __nv_bfloat16 b) {
    __nv_bfloat162 t(a, b);        // a -> low half (first in memory)
    return *(uint32_t*)&t;
}

// ---------------------------------------------------------------------------
// Kernel C v12: fused depthwise + bf16-pair WMMA GEMM (v11 + 3 CTAs/SM).
// ---------------------------------------------------------------------------
#define MPAD 136                      // halfword stride of A k-rows (272B)
#define KPAD 24                       // halfword stride of B f-rows (48B)
#define SS_STR 140                    // Ss float stride (conflict-free LDS.128)
// byte offsets into dynamic smem
#define AH0_B   26880                 // Ss = 3*16*140*4 = 26880 bytes at 0
#define AH1_B   31232                 // A tile = 16*136*2 = 4352 B each
#define AL0_B   35584
#define AL1_B   39936
#define BH0_B   44288                 // B tile = 64*24*2 = 3072 B each
#define BH1_B   47360
#define BL0_B   50432
#define BL1_B   53504
#define GEMM_SMEM_B 56576
#define CPAD 68                       // epilogue float stride (272B)

__global__ void __launch_bounds__(256, 3) dwpw_wmma(
        const float* __restrict__ dw_w,
        const float* __restrict__ dw_b,
        const float* __restrict__ pw_b,
        float* __restrict__ out) {
    extern __shared__ char smc[];
    float* Ss = (float*)smc;                     // [3*16][SS_STR], px at px+5

    int g   = blockIdx.y;
    int m0  = blockIdx.x * 128;
    int y   = blockIdx.x & 127;
    int tid = threadIdx.x;
    int wid = tid >> 5;

    const int warp_m = wid >> 1;
    const int warp_n = wid & 1;

    wmma::fragment<wmma::accumulator, 16, 16, 16, float> acc[2][2];
#pragma unroll
    for (int i = 0; i < 2; i++)
#pragma unroll
        for (int j = 0; j < 2; j++) wmma::fill_fragment(acc[i][j], 0.0f);

    // zero Ss halo columns (stored cols 4 and 133) for all 48 rows
    if (tid < 96) {
        int row = tid >> 1;
        Ss[row * SS_STR + ((tid & 1) ? 133 : 4)] = 0.f;
    }

    const float* gs  = g_samp_buf + (size_t)g * NPIX * KIN;
    const float* dwp = dw_w + (size_t)g * 9 * KIN;
    const __nv_bfloat16* pwh = g_pwh + (size_t)g * FG * KIN;
    const __nv_bfloat16* pwl = g_pwl + (size_t)g * FG * KIN;

    // depthwise mapping: thread = (akk, window of 8 consecutive pixels)
    const int akk   = tid & 15;
    const int halfh = (tid >> 4) & 1;
    const int wq    = tid >> 5;
    const int mg    = ((wq >> 1) * 4 + (wq & 1)) + 2 * halfh;
    const int xx0   = mg * 8;

    const int bfr = tid >> 2;         // B stage: f row 0..63
    const int bq  = tid & 3;          // B stage: 4-halfword quarter

    __syncthreads();                  // halo ready

    for (int kt = 0; kt < 36; kt++) {
        const int buf = kt & 1;
        __nv_bfloat16* Ah = (__nv_bfloat16*)(smc + (buf ? AH1_B : AH0_B));
        __nv_bfloat16* Al = (__nv_bfloat16*)(smc + (buf ? AL1_B : AL0_B));
        __nv_bfloat16* Bh = (__nv_bfloat16*)(smc + (buf ? BH1_B : BH0_B));
        __nv_bfloat16* Bl = (__nv_bfloat16*)(smc + (buf ? BL1_B : BL0_B));

        // ---- stage Ss: 3 rows x 16 kc x 128 px ----
#pragma unroll
        for (int p = 0; p < 6; p++) {
            int n   = tid + p * 256;        // < 1536
            int kc4 = n & 3;
            int xx  = (n >> 2) & 127;
            int r   = n >> 9;               // 0..2
            int yy  = y + r - 1;
            float4 v = make_float4(0.f, 0.f, 0.f, 0.f);
            if (yy >= 0 && yy < HH)
                v = *(const float4*)(gs +
                    (size_t)(m0 + (r - 1) * WW + xx) * KIN + kt * 16 + kc4 * 4);
            float* d = Ss + (r * 16 + kc4 * 4) * SS_STR + xx + 5;
            d[0]          = v.x;
            d[SS_STR]     = v.y;
            d[2 * SS_STR] = v.z;
            d[3 * SS_STR] = v.w;
        }
        // ---- stage B chunk (hi/lo) into buf: coalesced uint2 ----
        {
            size_t bsrc = ((size_t)bfr) * KIN + kt * 16 + bq * 4;
            uint2 vh = *(const uint2*)(pwh + bsrc);
            uint2 vl = *(const uint2*)(pwl + bsrc);
            *(uint2*)(Bh + bfr * KPAD + bq * 4) = vh;
            *(uint2*)(Bl + bfr * KPAD + bq * 4) = vl;
        }
        __syncthreads();        // Ss+B ready; all warps past mma(kt-1) -> A/B[buf] free

        // ---- depthwise: 8 consecutive pixels, vectorized reads + 16B writes ----
        {
            int kc = kt * 16 + akk;
            float bias = __ldg(dw_b + g * KIN + kc);
            float a[8];
#pragma unroll
            for (int i = 0; i < 8; i++) a[i] = bias;
#pragma unroll
            for (int jy = 0; jy < 3; jy++) {
                const float* rp = Ss + (jy * 16 + akk) * SS_STR + xx0 + 4;  // 16B-aligned
                float4 w03 = *(const float4*)(rp);
                float4 w47 = *(const float4*)(rp + 4);
                float2 w89 = *(const float2*)(rp + 8);
                float w[10] = {w03.x, w03.y, w03.z, w03.w,
                               w47.x, w47.y, w47.z, w47.w, w89.x, w89.y};
                float d0 = __ldg(dwp + (jy * 3 + 0) * KIN + kc);
                float d1 = __ldg(dwp + (jy * 3 + 1) * KIN + kc);
                float d2 = __ldg(dwp + (jy * 3 + 2) * KIN + kc);
#pragma unroll
                for (int i = 0; i < 8; i++)
                    a[i] += d0 * w[i] + d1 * w[i + 1] + d2 * w[i + 2];
            }
            __nv_bfloat16 hi[8], lo[8];
#pragma unroll
            for (int i = 0; i < 8; i++) {
                hi[i] = __float2bfloat16(a[i]);
                lo[i] = __float2bfloat16(a[i] - __bfloat162float(hi[i]));
            }
            uint4 hv = make_uint4(pack_bf2(hi[0], hi[1]), pack_bf2(hi[2], hi[3]),
                                  pack_bf2(hi[4], hi[5]), pack_bf2(hi[6], hi[7]));
            uint4 lv = make_uint4(pack_bf2(lo[0], lo[1]), pack_bf2(lo[2], lo[3]),
                                  pack_bf2(lo[4], lo[5]), pack_bf2(lo[6], lo[7]));
            *(uint4*)(Ah + akk * MPAD + xx0) = hv;   // col-major A: [k][m]
            *(uint4*)(Al + akk * MPAD + xx0) = lv;
        }
        __syncthreads();        // A ready; Ss free for next stage

        // ---- WMMA: A col-major + B col-major, both from smem ----
        {
            wmma::fragment<wmma::matrix_a, 16, 16, 16, __nv_bfloat16, wmma::col_major> ah[2], al[2];
            wmma::fragment<wmma::matrix_b, 16, 16, 16, __nv_bfloat16, wmma::col_major> bh[2], bl[2];
#pragma unroll
            for (int i = 0; i < 2; i++) {
                wmma::load_matrix_sync(ah[i], Ah + warp_m * 32 + i * 16, MPAD);
                wmma::load_matrix_sync(al[i], Al + warp_m * 32 + i * 16, MPAD);
            }
#pragma unroll
            for (int j = 0; j < 2; j++) {
                wmma::load_matrix_sync(bh[j], Bh + (warp_n * 32 + j * 16) * KPAD, KPAD);
                wmma::load_matrix_sync(bl[j], Bl + (warp_n * 32 + j * 16) * KPAD, KPAD);
            }
#pragma unroll
            for (int i = 0; i < 2; i++)
#pragma unroll
                for (int j = 0; j < 2; j++) {
                    wmma::mma_sync(acc[i][j], ah[i], bh[j], acc[i][j]);
                    wmma::mma_sync(acc[i][j], al[i], bh[j], acc[i][j]);
                    wmma::mma_sync(acc[i][j], ah[i], bl[j], acc[i][j]);
                }
        }
        // no barrier: next-iter sync covers the buffer swap
    }

    __syncthreads();                             // all MMA done before Cs overwrite
    // ---- epilogue: frags -> smem (stride CPAD) -> bias + coalesced stores ----
    float* Cs = (float*)smc;                     // [128][CPAD]
#pragma unroll
    for (int i = 0; i < 2; i++)
#pragma unroll
        for (int j = 0; j < 2; j++)
            wmma::store_matrix_sync(
                Cs + (warp_m * 32 + i * 16) * CPAD + warp_n * 32 + j * 16,
                acc[i][j], CPAD, wmma::mem_row_major);
    __syncthreads();

    for (int idx = tid; idx < 128 * 64; idx += 256) {
        int m = idx >> 6;
        int f = idx & 63;
        out[(size_t)(m0 + m) * CC + g * FG + f] = Cs[m * CPAD + f] + pw_b[g * FG + f];
    }
}

// ---------------------------------------------------------------------------
extern "C" void kernel_launch(void* const* d_in, const int* in_sizes, int n_in,
                              void* d_out, int out_size) {
    (void)in_sizes; (void)n_in; (void)out_size;
    const float* x     = (const float*)d_in[0];
    const float* off_w = (const float*)d_in[1];
    const float* off_b = (const float*)d_in[2];
    const float* dw_w  = (const float*)d_in[3];
    const float* dw_b  = (const float*)d_in[4];
    const float* pw_w  = (const float*)d_in[5];
    const float* pw_b  = (const float*)d_in[6];
    float* out = (float*)d_out;

    cudaFuncSetAttribute(offset_conv_v4,
                         cudaFuncAttributeMaxDynamicSharedMemorySize, OFFC2_SMEM);
    cudaFuncSetAttribute(dwpw_wmma,
                         cudaFuncAttributeMaxDynamicSharedMemorySize, GEMM_SMEM_B);

    // A: offsets (1024 blocks: g*b*row-pair*ci-half)
    offset_conv_v4<<<GG * BB * 64 * 2, 256, OFFC2_SMEM>>>(x, off_w, off_b);

    // Prep: pw hi/lo split (tiny)
    pw_split_kernel<<<(GG * KIN * FG + 255) / 256, 256>>>(pw_w);

    // B: bilinear sampling
    long long total_threads = (long long)GG * NPIX * 9 * 32;
    int blocks = (int)(total_threads / 256);
    sample_kernel<<<blocks, 256>>>(x);

    // C: fused depthwise + WMMA pointwise
    dim3 grid(NPIX / 128, GG);
    dwpw_wmma<<<grid, 256, GEMM_SMEM_B>>>(dw_w, dw_b, pw_b, out);
}

// round 16
// speedup vs baseline: 1.1738x; 1.1738x over previous
#include <cuda_runtime.h>
#include <cuda_bf16.h>
#include <mma.h>
#include <cstdint>

using namespace nvcuda;

#define HH 128
#define WW 128
#define BB 4
#define CC 128
#define GG 2
#define CG 64
#define KIN 576   // 9*64
#define FG 64
#define NPIX (BB*HH*WW)   // 65536

// ---------------- offset conv smem config (v3) ----------------
#define XSTR 533
#define XS_FLOATS (64 * XSTR)
#define SW_FLOATS (9 * 64 * 20)
#define OFFC_SMEM ((XS_FLOATS + SW_FLOATS) * 4)  // 182528 bytes

// ---------------- scratch globals ----------------
__device__ float g_off_buf[(size_t)GG * NPIX * 18];
__device__ float g_samp_buf[(size_t)GG * NPIX * KIN];          // 302MB
__device__ __nv_bfloat16 g_pwh[(size_t)GG * FG * KIN];         // pw hi, [g][f][kin]
__device__ __nv_bfloat16 g_pwl[(size_t)GG * FG * KIN];         // pw lo

// ---------------------------------------------------------------------------
// Kernel A v3 (reverted to the known-good 135us version): offset conv
// ---------------------------------------------------------------------------
__global__ void __launch_bounds__(256) offset_conv_v3(
        const float* __restrict__ x,
        const float* __restrict__ off_w,
        const float* __restrict__ off_b) {
    extern __shared__ float sm[];
    float* Xs = sm;
    float* sw = sm + XS_FLOATS;

    int bid = blockIdx.x;
    int g   = bid >> 8;
    int rem = bid & 255;
    int b   = rem >> 6;
    int y0  = (rem & 63) << 1;
    int tid = threadIdx.x;

    const float* wsrc = off_w + (size_t)g * 10368;
    for (int i = tid; i < 10368; i += 256) {
        int oc = i % 18;
        int jc = i / 18;
        sw[jc * 20 + oc] = wsrc[i];
    }
    for (int i = tid; i < 64 * 4 * 2; i += 256) {
        int ci   = i >> 3;
        int r    = (i >> 1) & 3;
        int cpos = (i & 1) ? 129 : 0;
        Xs[ci * XSTR + r * 133 + cpos] = 0.f;
    }
    if (y0 == 0) {
        for (int i = tid; i < 64 * 130; i += 256)
            Xs[(i / 130) * XSTR + (i % 130)] = 0.f;
    }
    if (y0 == HH - 2) {
        for (int i = tid; i < 64 * 130; i += 256)
            Xs[(i / 130) * XSTR + 3 * 133 + (i % 130)] = 0.f;
    }
    for (int i = tid; i < 4 * 128 * 16; i += 256) {
        int c4 = i & 15;
        int t  = i >> 4;
        int px = t & 127;
        int r  = t >> 7;
        int yy = y0 - 1 + r;
        if (yy < 0 || yy >= HH) continue;
        const float4 v = *(const float4*)(x +
            (((size_t)(b * HH + yy) * WW + px) * CC + g * CG + c4 * 4));
        int base = r * 133 + px + 1;
        Xs[(c4 * 4 + 0) * XSTR + base] = v.x;
        Xs[(c4 * 4 + 1) * XSTR + base] = v.y;
        Xs[(c4 * 4 + 2) * XSTR + base] = v.z;
        Xs[(c4 * 4 + 3) * XSTR + base] = v.w;
    }
    __syncthreads();

    int px   = tid & 127;
    int rsel = tid >> 7;
    float acc[18];
#pragma unroll
    for (int oc = 0; oc < 18; oc++) acc[oc] = off_b[g * 18 + oc];

    for (int ci = 0; ci < 64; ci++) {
        const float* xp = Xs + ci * XSTR + rsel * 133 + px;
        float xv[3][3];
#pragma unroll
        for (int r = 0; r < 3; r++)
#pragma unroll
            for (int k = 0; k < 3; k++)
                xv[r][k] = xp[r * 133 + k];

        const float* wbase = sw + ci * 20;
#pragma unroll
        for (int ky = 0; ky < 3; ky++) {
#pragma unroll
            for (int kx = 0; kx < 3; kx++) {
                const float* w = wbase + (ky * 3 + kx) * (64 * 20);
                float4 w0 = *(const float4*)(w);
                float4 w1 = *(const float4*)(w + 4);
                float4 w2 = *(const float4*)(w + 8);
                float4 w3 = *(const float4*)(w + 12);
                float2 w4 = *(const float2*)(w + 16);
                float a = xv[ky][kx];
                float wv[18] = {w0.x,w0.y,w0.z,w0.w, w1.x,w1.y,w1.z,w1.w,
                                w2.x,w2.y,w2.z,w2.w, w3.x,w3.y,w3.z,w3.w,
                                w4.x,w4.y};
#pragma unroll
                for (int oc = 0; oc < 18; oc++) acc[oc] += a * wv[oc];
            }
        }
    }

    int m = (b * HH + y0 + rsel) * WW + px;
    float* op = g_off_buf + ((size_t)g * NPIX + m) * 18;
#pragma unroll
    for (int oc = 0; oc < 18; oc++) op[oc] = acc[oc];
}

// ---------------------------------------------------------------------------
// Kernel B: bilinear sampling, float2-vectorized (single offset buffer).
// ---------------------------------------------------------------------------
__global__ void sample_kernel(const float* __restrict__ x) {
    int wid  = (blockIdx.x * blockDim.x + threadIdx.x) >> 5;
    int lane = threadIdx.x & 31;
    int k = wid % 9;
    int t = wid / 9;
    int m = t & (NPIX - 1);
    int g = t >> 16;

    int b    = m >> 14;
    int y    = (m >> 7) & 127;
    int xpix = m & 127;

    const float* offp = g_off_buf + ((size_t)g * NPIX + m) * 18 + 2 * k;
    float ox = offp[0];
    float oy = offp[1];

    float fx = (float)xpix + (float)(k % 3 - 1) + ox;
    float fy = (float)y    + (float)(k / 3 - 1) + oy;
    fx = fminf(fmaxf(fx, 0.f), (float)(WW - 1));
    fy = fminf(fmaxf(fy, 0.f), (float)(HH - 1));

    float x0f = floorf(fx), y0f = floorf(fy);
    float x1f = fminf(x0f + 1.f, (float)(WW - 1));
    float y1f = fminf(y0f + 1.f, (float)(HH - 1));

    float tx  = fx - x0f, ty  = fy - y0f;
    float txc = x1f - fx, tyc = y1f - fy;
    float wa = txc * tyc;
    float wb = txc * ty;
    float wc = tx  * tyc;
    float wd = tx  * ty;

    int x0 = (int)x0f, x1 = (int)x1f, y0 = (int)y0f, y1 = (int)y1f;

    const float* base = x + (size_t)b * HH * WW * CC + g * CG;
    const float2* p00 = (const float2*)(base + ((size_t)y0 * WW + x0) * CC) + lane;
    const float2* p10 = (const float2*)(base + ((size_t)y1 * WW + x0) * CC) + lane;
    const float2* p01 = (const float2*)(base + ((size_t)y0 * WW + x1) * CC) + lane;
    const float2* p11 = (const float2*)(base + ((size_t)y1 * WW + x1) * CC) + lane;

    float2 a = __ldg(p00), bb2 = __ldg(p10), c2 = __ldg(p01), d2 = __ldg(p11);
    float2 v;
    v.x = wa * a.x + wb * bb2.x + wc * c2.x + wd * d2.x;
    v.y = wa * a.y + wb * bb2.y + wc * c2.y + wd * d2.y;

    float2* sp = (float2*)(g_samp_buf + ((size_t)g * NPIX + m) * KIN + k * CG) + lane;
    *sp = v;
}

// ---------------------------------------------------------------------------
// Prep: split pw weights into bf16 hi/lo, transposed to [g][f][kin].
// ---------------------------------------------------------------------------
__global__ void pw_split_kernel(const float* __restrict__ pw_w) {
    int idx = blockIdx.x * blockDim.x + threadIdx.x;
    if (idx >= GG * KIN * FG) return;
    int f   = idx & 63;
    int kin = (idx >> 6) % KIN;
    int g   = idx / (KIN * FG);
    float v = pw_w[idx];
    __nv_bfloat16 hi = __float2bfloat16(v);
    __nv_bfloat16 lo = __float2bfloat16(v - __bfloat162float(hi));
    size_t o = ((size_t)g * FG + f) * KIN + kin;
    g_pwh[o] = hi;
    g_pwl[o] = lo;
}

__device__ __forceinline__ uint32_t pack_bf2(__nv_bfloat16 a, __nv_bfloat16 b) {
    __nv_bfloat162 t(a, b);        // a -> low half (first in memory)
    return *(uint32_t*)&t;
}

// ---------------------------------------------------------------------------
// Kernel C v13: fused depthwise + bf16-pair WMMA GEMM.
//  - NO Ss smem stage: depthwise reads straight from global (predicated LDGs,
//    lanes cover 16 consecutive channels -> 64B segments, L1-cached)
//  - A tiles col-major [k][m], 2x STS.128 per thread
//  - B staged in smem per chunk (double-buffered)
//  - ONE barrier per chunk
// ---------------------------------------------------------------------------
#define MPAD 136                      // halfword stride of A k-rows (272B)
#define KPAD 24                       // halfword stride of B f-rows (48B)
// byte offsets into dynamic smem
#define AH0_B   0                     // A tile = 16*136*2 = 4352 B each
#define AH1_B   4352
#define AL0_B   8704
#define AL1_B   13056
#define BH0_B   17408                 // B tile = 64*24*2 = 3072 B each
#define BH1_B   20480
#define BL0_B   23552
#define BL1_B   26624
#define GEMM_SMEM_B 34816             // epilogue Cs [128][68] floats dominates
#define CPAD 68                       // epilogue float stride (272B)

__global__ void __launch_bounds__(256, 3) dwpw_wmma(
        const float* __restrict__ dw_w,
        const float* __restrict__ dw_b,
        const float* __restrict__ pw_b,
        float* __restrict__ out) {
    extern __shared__ char smc[];

    int g   = blockIdx.y;
    int m0  = blockIdx.x * 128;
    int y   = blockIdx.x & 127;
    int tid = threadIdx.x;
    int wid = tid >> 5;

    const int warp_m = wid >> 1;
    const int warp_n = wid & 1;

    wmma::fragment<wmma::accumulator, 16, 16, 16, float> acc[2][2];
#pragma unroll
    for (int i = 0; i < 2; i++)
#pragma unroll
        for (int j = 0; j < 2; j++) wmma::fill_fragment(acc[i][j], 0.0f);

    const float* gs  = g_samp_buf + (size_t)g * NPIX * KIN;
    const float* dwp = dw_w + (size_t)g * 9 * KIN;
    const __nv_bfloat16* pwh = g_pwh + (size_t)g * FG * KIN;
    const __nv_bfloat16* pwl = g_pwl + (size_t)g * FG * KIN;

    // depthwise mapping: thread = (akk channel, window of 8 consecutive pixels)
    const int akk   = tid & 15;
    const int halfh = (tid >> 4) & 1;
    const int wq    = tid >> 5;
    const int mg    = ((wq >> 1) * 4 + (wq & 1)) + 2 * halfh;   // 0..15
    const int xx0   = mg * 8;

    const int bfr = tid >> 2;         // B stage: f row 0..63
    const int bq  = tid & 3;          // B stage: 4-halfword quarter

    for (int kt = 0; kt < 36; kt++) {
        const int buf = kt & 1;
        __nv_bfloat16* Ah = (__nv_bfloat16*)(smc + (buf ? AH1_B : AH0_B));
        __nv_bfloat16* Al = (__nv_bfloat16*)(smc + (buf ? AL1_B : AL0_B));
        __nv_bfloat16* Bh = (__nv_bfloat16*)(smc + (buf ? BH1_B : BH0_B));
        __nv_bfloat16* Bl = (__nv_bfloat16*)(smc + (buf ? BL1_B : BL0_B));

        // ---- stage B chunk (hi/lo) into buf: coalesced uint2 ----
        {
            size_t bsrc = ((size_t)bfr) * KIN + kt * 16 + bq * 4;
            uint2 vh = *(const uint2*)(pwh + bsrc);
            uint2 vl = *(const uint2*)(pwl + bsrc);
            *(uint2*)(Bh + bfr * KPAD + bq * 4) = vh;
            *(uint2*)(Bl + bfr * KPAD + bq * 4) = vl;
        }

        // ---- depthwise: 8 consecutive pixels, direct from global ----
        {
            int kc = kt * 16 + akk;
            float bias = __ldg(dw_b + g * KIN + kc);
            float a[8];
#pragma unroll
            for (int i = 0; i < 8; i++) a[i] = bias;
#pragma unroll
            for (int jy = 0; jy < 3; jy++) {
                int yy = y + jy - 1;
                bool yok = (yy >= 0) && (yy < HH);
                const float* rowp = gs + ((size_t)(m0 + (jy - 1) * WW) * KIN
                                          + kt * 16 + akk);
                float w[10];
#pragma unroll
                for (int q = 0; q < 10; q++) {
                    int pxin = xx0 - 1 + q;
                    bool ok = yok && (pxin >= 0) && (pxin < WW);
                    w[q] = ok ? __ldg(rowp + (size_t)pxin * KIN) : 0.f;
                }
                float d0 = __ldg(dwp + (jy * 3 + 0) * KIN + kc);
                float d1 = __ldg(dwp + (jy * 3 + 1) * KIN + kc);
                float d2 = __ldg(dwp + (jy * 3 + 2) * KIN + kc);
#pragma unroll
                for (int i = 0; i < 8; i++)
                    a[i] += d0 * w[i] + d1 * w[i + 1] + d2 * w[i + 2];
            }
            __nv_bfloat16 hi[8], lo[8];
#pragma unroll
            for (int i = 0; i < 8; i++) {
                hi[i] = __float2bfloat16(a[i]);
                lo[i] = __float2bfloat16(a[i] - __bfloat162float(hi[i]));
            }
            uint4 hv = make_uint4(pack_bf2(hi[0], hi[1]), pack_bf2(hi[2], hi[3]),
                                  pack_bf2(hi[4], hi[5]), pack_bf2(hi[6], hi[7]));
            uint4 lv = make_uint4(pack_bf2(lo[0], lo[1]), pack_bf2(lo[2], lo[3]),
                                  pack_bf2(lo[4], lo[5]), pack_bf2(lo[6], lo[7]));
            *(uint4*)(Ah + akk * MPAD + xx0) = hv;   // col-major A: [k][m]
            *(uint4*)(Al + akk * MPAD + xx0) = lv;
        }
        __syncthreads();        // A+B[buf] ready (and A/B[buf] free: mma(kt-2)
                                // finished before sync(kt-1))

        // ---- WMMA: A col-major + B col-major, both from smem ----
        {
            wmma::fragment<wmma::matrix_a, 16, 16, 16, __nv_bfloat16, wmma::col_major> ah[2], al[2];
            wmma::fragment<wmma::matrix_b, 16, 16, 16, __nv_bfloat16, wmma::col_major> bh[2], bl[2];
#pragma unroll
            for (int i = 0; i < 2; i++) {
                wmma::load_matrix_sync(ah[i], Ah + warp_m * 32 + i * 16, MPAD);
                wmma::load_matrix_sync(al[i], Al + warp_m * 32 + i * 16, MPAD);
            }
#pragma unroll
            for (int j = 0; j < 2; j++) {
                wmma::load_matrix_sync(bh[j], Bh + (warp_n * 32 + j * 16) * KPAD, KPAD);
                wmma::load_matrix_sync(bl[j], Bl + (warp_n * 32 + j * 16) * KPAD, KPAD);
            }
#pragma unroll
            for (int i = 0; i < 2; i++)
#pragma unroll
                for (int j = 0; j < 2; j++) {
                    wmma::mma_sync(acc[i][j], ah[i], bh[j], acc[i][j]);
                    wmma::mma_sync(acc[i][j], al[i], bh[j], acc[i][j]);
                    wmma::mma_sync(acc[i][j], ah[i], bl[j], acc[i][j]);
                }
        }
        // no trailing barrier: double buffer + next-iter sync covers the swap
    }

    __syncthreads();                             // all MMA done before Cs overwrite
    // ---- epilogue: frags -> smem (stride CPAD) -> bias + coalesced stores ----
    float* Cs = (float*)smc;                     // [128][CPAD]
#pragma unroll
    for (int i = 0; i < 2; i++)
#pragma unroll
        for (int j = 0; j < 2; j++)
            wmma::store_matrix_sync(
                Cs + (warp_m * 32 + i * 16) * CPAD + warp_n * 32 + j * 16,
                acc[i][j], CPAD, wmma::mem_row_major);
    __syncthreads();

    for (int idx = tid; idx < 128 * 64; idx += 256) {
        int m = idx >> 6;
        int f = idx & 63;
        out[(size_t)(m0 + m) * CC + g * FG + f] = Cs[m * CPAD + f] + pw_b[g * FG + f];
    }
}

// ---------------------------------------------------------------------------
extern "C" void kernel_launch(void* const* d_in, const int* in_sizes, int n_in,
                              void* d_out, int out_size) {
    (void)in_sizes; (void)n_in; (void)out_size;
    const float* x     = (const float*)d_in[0];
    const float* off_w = (const float*)d_in[1];
    const float* off_b = (const float*)d_in[2];
    const float* dw_w  = (const float*)d_in[3];
    const float* dw_b  = (const float*)d_in[4];
    const float* pw_w  = (const float*)d_in[5];
    const float* pw_b  = (const float*)d_in[6];
    float* out = (float*)d_out;

    cudaFuncSetAttribute(offset_conv_v3,
                         cudaFuncAttributeMaxDynamicSharedMemorySize, OFFC_SMEM);
    cudaFuncSetAttribute(dwpw_wmma,
                         cudaFuncAttributeMaxDynamicSharedMemorySize, GEMM_SMEM_B);

    // A: offsets
    offset_conv_v3<<<GG * BB * 64, 256, OFFC_SMEM>>>(x, off_w, off_b);

    // Prep: pw hi/lo split (tiny)
    pw_split_kernel<<<(GG * KIN * FG + 255) / 256, 256>>>(pw_w);

    // B: bilinear sampling
    long long total_threads = (long long)GG * NPIX * 9 * 32;
    int blocks = (int)(total_threads / 256);
    sample_kernel<<<blocks, 256>>>(x);

    // C: fused depthwise + WMMA pointwise
    dim3 grid(NPIX / 128, GG);
    dwpw_wmma<<<grid, 256, GEMM_SMEM_B>>>(dw_w, dw_b, pw_b, out);
}

// round 17
// speedup vs baseline: 1.1768x; 1.0026x over previous
#include <cuda_runtime.h>
#include <cuda_bf16.h>
#include <cuda_fp16.h>
#include <mma.h>
#include <cstdint>

using namespace nvcuda;

#define HH 128
#define WW 128
#define BB 4
#define CC 128
#define GG 2
#define CG 64
#define KIN 576   // 9*64
#define FG 64
#define NPIX (BB*HH*WW)   // 65536

// ---------------- offset conv smem config ----------------
#define XSTR 533
#define XS_FLOATS (64 * XSTR)
#define SW_FLOATS (9 * 64 * 20)
#define OFFC_SMEM ((XS_FLOATS + SW_FLOATS) * 4)  // 182528 bytes

// ---------------- scratch globals ----------------
__device__ float g_off_buf[(size_t)GG * NPIX * 18];
__device__ __half g_samp_h[(size_t)GG * NPIX * KIN];           // 151MB (fp16)
__device__ __nv_bfloat16 g_pwh[(size_t)GG * FG * KIN];         // pw hi, [g][f][kin]
__device__ __nv_bfloat16 g_pwl[(size_t)GG * FG * KIN];         // pw lo

// ---------------------------------------------------------------------------
// Kernel A v5: offset conv, 512 threads = (px, rsel, ci-half).
// Same staging/smem as v3; ci-split doubles warps/SM (8 -> 16).
// Halves combined via reduction in the (dead) weight-smem region.
// ---------------------------------------------------------------------------
__global__ void __launch_bounds__(512) offset_conv_v5(
        const float* __restrict__ x,
        const float* __restrict__ off_w,
        const float* __restrict__ off_b) {
    extern __shared__ float sm[];
    float* Xs = sm;
    float* sw = sm + XS_FLOATS;

    int bid = blockIdx.x;
    int g   = bid >> 8;
    int rem = bid & 255;
    int b   = rem >> 6;
    int y0  = (rem & 63) << 1;
    int tid = threadIdx.x;            // 512

    const float* wsrc = off_w + (size_t)g * 10368;
    for (int i = tid; i < 10368; i += 512) {
        int oc = i % 18;
        int jc = i / 18;
        sw[jc * 20 + oc] = wsrc[i];
    }
    if (tid < 512) {                  // halo cols: 64*4*2 = 512
        int i  = tid;
        int ci = i >> 3;
        int r  = (i >> 1) & 3;
        int cpos = (i & 1) ? 129 : 0;
        Xs[ci * XSTR + r * 133 + cpos] = 0.f;
    }
    if (y0 == 0) {
        for (int i = tid; i < 64 * 130; i += 512)
            Xs[(i / 130) * XSTR + (i % 130)] = 0.f;
    }
    if (y0 == HH - 2) {
        for (int i = tid; i < 64 * 130; i += 512)
            Xs[(i / 130) * XSTR + 3 * 133 + (i % 130)] = 0.f;
    }
    for (int i = tid; i < 4 * 128 * 16; i += 512) {
        int c4 = i & 15;
        int t  = i >> 4;
        int px = t & 127;
        int r  = t >> 7;
        int yy = y0 - 1 + r;
        if (yy < 0 || yy >= HH) continue;
        const float4 v = *(const float4*)(x +
            (((size_t)(b * HH + yy) * WW + px) * CC + g * CG + c4 * 4));
        int base = r * 133 + px + 1;
        Xs[(c4 * 4 + 0) * XSTR + base] = v.x;
        Xs[(c4 * 4 + 1) * XSTR + base] = v.y;
        Xs[(c4 * 4 + 2) * XSTR + base] = v.z;
        Xs[(c4 * 4 + 3) * XSTR + base] = v.w;
    }
    __syncthreads();

    int px   = tid & 127;
    int rsel = (tid >> 7) & 1;
    int half = tid >> 8;              // ci-half
    float acc[18];
#pragma unroll
    for (int oc = 0; oc < 18; oc++)
        acc[oc] = half ? 0.f : off_b[g * 18 + oc];

    for (int cii = 0; cii < 32; cii++) {
        int ci = half * 32 + cii;
        const float* xp = Xs + ci * XSTR + rsel * 133 + px;
        float xv[3][3];
#pragma unroll
        for (int r = 0; r < 3; r++)
#pragma unroll
            for (int k = 0; k < 3; k++)
                xv[r][k] = xp[r * 133 + k];

        const float* wbase = sw + ci * 20;
#pragma unroll
        for (int ky = 0; ky < 3; ky++) {
#pragma unroll
            for (int kx = 0; kx < 3; kx++) {
                const float* w = wbase + (ky * 3 + kx) * (64 * 20);
                float4 w0 = *(const float4*)(w);
                float4 w1 = *(const float4*)(w + 4);
                float4 w2 = *(const float4*)(w + 8);
                float4 w3 = *(const float4*)(w + 12);
                float2 w4 = *(const float2*)(w + 16);
                float a = xv[ky][kx];
                float wv[18] = {w0.x,w0.y,w0.z,w0.w, w1.x,w1.y,w1.z,w1.w,
                                w2.x,w2.y,w2.z,w2.w, w3.x,w3.y,w3.z,w3.w,
                                w4.x,w4.y};
#pragma unroll
                for (int oc = 0; oc < 18; oc++) acc[oc] += a * wv[oc];
            }
        }
    }

    // ---- combine halves via smem (weights region now dead) ----
    __syncthreads();
    float* red = sw;                  // [256][19]
    if (half == 1) {
#pragma unroll
        for (int oc = 0; oc < 18; oc++)
            red[(rsel * 128 + px) * 19 + oc] = acc[oc];
    }
    __syncthreads();
    if (half == 0) {
        int m = (b * HH + y0 + rsel) * WW + px;
        float* op = g_off_buf + ((size_t)g * NPIX + m) * 18;
        const float* rp = red + (rsel * 128 + px) * 19;
#pragma unroll
        for (int oc = 0; oc < 18; oc++) op[oc] = acc[oc] + rp[oc];
    }
}

// ---------------------------------------------------------------------------
// Kernel B: bilinear sampling -> fp16 samp buffer.
// ---------------------------------------------------------------------------
__global__ void sample_kernel(const float* __restrict__ x) {
    int wid  = (blockIdx.x * blockDim.x + threadIdx.x) >> 5;
    int lane = threadIdx.x & 31;
    int k = wid % 9;
    int t = wid / 9;
    int m = t & (NPIX - 1);
    int g = t >> 16;

    int b    = m >> 14;
    int y    = (m >> 7) & 127;
    int xpix = m & 127;

    const float* offp = g_off_buf + ((size_t)g * NPIX + m) * 18 + 2 * k;
    float ox = offp[0];
    float oy = offp[1];

    float fx = (float)xpix + (float)(k % 3 - 1) + ox;
    float fy = (float)y    + (float)(k / 3 - 1) + oy;
    fx = fminf(fmaxf(fx, 0.f), (float)(WW - 1));
    fy = fminf(fmaxf(fy, 0.f), (float)(HH - 1));

    float x0f = floorf(fx), y0f = floorf(fy);
    float x1f = fminf(x0f + 1.f, (float)(WW - 1));
    float y1f = fminf(y0f + 1.f, (float)(HH - 1));

    float tx  = fx - x0f, ty  = fy - y0f;
    float txc = x1f - fx, tyc = y1f - fy;
    float wa = txc * tyc;
    float wb = txc * ty;
    float wc = tx  * tyc;
    float wd = tx  * ty;

    int x0 = (int)x0f, x1 = (int)x1f, y0 = (int)y0f, y1 = (int)y1f;

    const float* base = x + (size_t)b * HH * WW * CC + g * CG;
    const float2* p00 = (const float2*)(base + ((size_t)y0 * WW + x0) * CC) + lane;
    const float2* p10 = (const float2*)(base + ((size_t)y1 * WW + x0) * CC) + lane;
    const float2* p01 = (const float2*)(base + ((size_t)y0 * WW + x1) * CC) + lane;
    const float2* p11 = (const float2*)(base + ((size_t)y1 * WW + x1) * CC) + lane;

    float2 a = __ldg(p00), bb2 = __ldg(p10), c2 = __ldg(p01), d2 = __ldg(p11);
    float2 v;
    v.x = wa * a.x + wb * bb2.x + wc * c2.x + wd * d2.x;
    v.y = wa * a.y + wb * bb2.y + wc * c2.y + wd * d2.y;

    __half2* sp = (__half2*)(g_samp_h + ((size_t)g * NPIX + m) * KIN + k * CG) + lane;
    *sp = __floats2half2_rn(v.x, v.y);
}

// ---------------------------------------------------------------------------
// Prep: split pw weights into bf16 hi/lo, transposed to [g][f][kin].
// ---------------------------------------------------------------------------
__global__ void pw_split_kernel(const float* __restrict__ pw_w) {
    int idx = blockIdx.x * blockDim.x + threadIdx.x;
    if (idx >= GG * KIN * FG) return;
    int f   = idx & 63;
    int kin = (idx >> 6) % KIN;
    int g   = idx / (KIN * FG);
    float v = pw_w[idx];
    __nv_bfloat16 hi = __float2bfloat16(v);
    __nv_bfloat16 lo = __float2bfloat16(v - __bfloat162float(hi));
    size_t o = ((size_t)g * FG + f) * KIN + kin;
    g_pwh[o] = hi;
    g_pwl[o] = lo;
}

__device__ __forceinline__ uint32_t pack_bf2(__nv_bfloat16 a, __nv_bfloat16 b) {
    __nv_bfloat162 t(a, b);        // a -> low half (first in memory)
    return *(uint32_t*)&t;
}

// ---------------------------------------------------------------------------
// Kernel C v13h: fused depthwise + bf16-pair WMMA GEMM (fp16 samp input).
// ---------------------------------------------------------------------------
#define MPAD 136                      // halfword stride of A k-rows (272B)
#define KPAD 24                       // halfword stride of B f-rows (48B)
// byte offsets into dynamic smem
#define AH0_B   0                     // A tile = 16*136*2 = 4352 B each
#define AH1_B   4352
#define AL0_B   8704
#define AL1_B   13056
#define BH0_B   17408                 // B tile = 64*24*2 = 3072 B each
#define BH1_B   20480
#define BL0_B   23552
#define BL1_B   26624
#define GEMM_SMEM_B 34816             // epilogue Cs [128][68] floats dominates
#define CPAD 68                       // epilogue float stride (272B)

__global__ void __launch_bounds__(256, 3) dwpw_wmma(
        const float* __restrict__ dw_w,
        const float* __restrict__ dw_b,
        const float* __restrict__ pw_b,
        float* __restrict__ out) {
    extern __shared__ char smc[];

    int g   = blockIdx.y;
    int m0  = blockIdx.x * 128;
    int y   = blockIdx.x & 127;
    int tid = threadIdx.x;
    int wid = tid >> 5;

    const int warp_m = wid >> 1;
    const int warp_n = wid & 1;

    wmma::fragment<wmma::accumulator, 16, 16, 16, float> acc[2][2];
#pragma unroll
    for (int i = 0; i < 2; i++)
#pragma unroll
        for (int j = 0; j < 2; j++) wmma::fill_fragment(acc[i][j], 0.0f);

    const __half* gs = g_samp_h + (size_t)g * NPIX * KIN;
    const float* dwp = dw_w + (size_t)g * 9 * KIN;
    const __nv_bfloat16* pwh = g_pwh + (size_t)g * FG * KIN;
    const __nv_bfloat16* pwl = g_pwl + (size_t)g * FG * KIN;

    // depthwise mapping: thread = (akk channel, window of 8 consecutive pixels)
    const int akk   = tid & 15;
    const int halfh = (tid >> 4) & 1;
    const int wq    = tid >> 5;
    const int mg    = ((wq >> 1) * 4 + (wq & 1)) + 2 * halfh;   // 0..15
    const int xx0   = mg * 8;

    const int bfr = tid >> 2;         // B stage: f row 0..63
    const int bq  = tid & 3;          // B stage: 4-halfword quarter

    for (int kt = 0; kt < 36; kt++) {
        const int buf = kt & 1;
        __nv_bfloat16* Ah = (__nv_bfloat16*)(smc + (buf ? AH1_B : AH0_B));
        __nv_bfloat16* Al = (__nv_bfloat16*)(smc + (buf ? AL1_B : AL0_B));
        __nv_bfloat16* Bh = (__nv_bfloat16*)(smc + (buf ? BH1_B : BH0_B));
        __nv_bfloat16* Bl = (__nv_bfloat16*)(smc + (buf ? BL1_B : BL0_B));

        // ---- stage B chunk (hi/lo) into buf: coalesced uint2 ----
        {
            size_t bsrc = ((size_t)bfr) * KIN + kt * 16 + bq * 4;
            uint2 vh = *(const uint2*)(pwh + bsrc);
            uint2 vl = *(const uint2*)(pwl + bsrc);
            *(uint2*)(Bh + bfr * KPAD + bq * 4) = vh;
            *(uint2*)(Bl + bfr * KPAD + bq * 4) = vl;
        }

        // ---- depthwise: 8 consecutive pixels, direct from global fp16 ----
        {
            int kc = kt * 16 + akk;
            float bias = __ldg(dw_b + g * KIN + kc);
            float a[8];
#pragma unroll
            for (int i = 0; i < 8; i++) a[i] = bias;
#pragma unroll
            for (int jy = 0; jy < 3; jy++) {
                int yy = y + jy - 1;
                bool yok = (yy >= 0) && (yy < HH);
                const __half* rowp = gs + ((size_t)(m0 + (jy - 1) * WW) * KIN
                                           + kt * 16 + akk);
                float w[10];
#pragma unroll
                for (int q = 0; q < 10; q++) {
                    int pxin = xx0 - 1 + q;
                    bool ok = yok && (pxin >= 0) && (pxin < WW);
                    w[q] = ok ? __half2float(__ldg(rowp + (size_t)pxin * KIN)) : 0.f;
                }
                float d0 = __ldg(dwp + (jy * 3 + 0) * KIN + kc);
                float d1 = __ldg(dwp + (jy * 3 + 1) * KIN + kc);
                float d2 = __ldg(dwp + (jy * 3 + 2) * KIN + kc);
#pragma unroll
                for (int i = 0; i < 8; i++)
                    a[i] += d0 * w[i] + d1 * w[i + 1] + d2 * w[i + 2];
            }
            __nv_bfloat16 hi[8], lo[8];
#pragma unroll
            for (int i = 0; i < 8; i++) {
                hi[i] = __float2bfloat16(a[i]);
                lo[i] = __float2bfloat16(a[i] - __bfloat162float(hi[i]));
            }
            uint4 hv = make_uint4(pack_bf2(hi[0], hi[1]), pack_bf2(hi[2], hi[3]),
                                  pack_bf2(hi[4], hi[5]), pack_bf2(hi[6], hi[7]));
            uint4 lv = make_uint4(pack_bf2(lo[0], lo[1]), pack_bf2(lo[2], lo[3]),
                                  pack_bf2(lo[4], lo[5]), pack_bf2(lo[6], lo[7]));
            *(uint4*)(Ah + akk * MPAD + xx0) = hv;   // col-major A: [k][m]
            *(uint4*)(Al + akk * MPAD + xx0) = lv;
        }
        __syncthreads();        // A+B[buf] ready

        // ---- WMMA: A col-major + B col-major, both from smem ----
        {
            wmma::fragment<wmma::matrix_a, 16, 16, 16, __nv_bfloat16, wmma::col_major> ah[2], al[2];
            wmma::fragment<wmma::matrix_b, 16, 16, 16, __nv_bfloat16, wmma::col_major> bh[2], bl[2];
#pragma unroll
            for (int i = 0; i < 2; i++) {
                wmma::load_matrix_sync(ah[i], Ah + warp_m * 32 + i * 16, MPAD);
                wmma::load_matrix_sync(al[i], Al + warp_m * 32 + i * 16, MPAD);
            }
#pragma unroll
            for (int j = 0; j < 2; j++) {
                wmma::load_matrix_sync(bh[j], Bh + (warp_n * 32 + j * 16) * KPAD, KPAD);
                wmma::load_matrix_sync(bl[j], Bl + (warp_n * 32 + j * 16) * KPAD, KPAD);
            }
#pragma unroll
            for (int i = 0; i < 2; i++)
#pragma unroll
                for (int j = 0; j < 2; j++) {
                    wmma::mma_sync(acc[i][j], ah[i], bh[j], acc[i][j]);
                    wmma::mma_sync(acc[i][j], al[i], bh[j], acc[i][j]);
                    wmma::mma_sync(acc[i][j], ah[i], bl[j], acc[i][j]);
                }
        }
        // no trailing barrier: double buffer + next-iter sync covers the swap
    }

    __syncthreads();                             // all MMA done before Cs overwrite
    // ---- epilogue: frags -> smem (stride CPAD) -> bias + coalesced stores ----
    float* Cs = (float*)smc;                     // [128][CPAD]
#pragma unroll
    for (int i = 0; i < 2; i++)
#pragma unroll
        for (int j = 0; j < 2; j++)
            wmma::store_matrix_sync(
                Cs + (warp_m * 32 + i * 16) * CPAD + warp_n * 32 + j * 16,
                acc[i][j], CPAD, wmma::mem_row_major);
    __syncthreads();

    for (int idx = tid; idx < 128 * 64; idx += 256) {
        int m = idx >> 6;
        int f = idx & 63;
        out[(size_t)(m0 + m) * CC + g * FG + f] = Cs[m * CPAD + f] + pw_b[g * FG + f];
    }
}

// ---------------------------------------------------------------------------
extern "C" void kernel_launch(void* const* d_in, const int* in_sizes, int n_in,
                              void* d_out, int out_size) {
    (void)in_sizes; (void)n_in; (void)out_size;
    const float* x     = (const float*)d_in[0];
    const float* off_w = (const float*)d_in[1];
    const float* off_b = (const float*)d_in[2];
    const float* dw_w  = (const float*)d_in[3];
    const float* dw_b  = (const float*)d_in[4];
    const float* pw_w  = (const float*)d_in[5];
    const float* pw_b  = (const float*)d_in[6];
    float* out = (float*)d_out;

    cudaFuncSetAttribute(offset_conv_v5,
                         cudaFuncAttributeMaxDynamicSharedMemorySize, OFFC_SMEM);
    cudaFuncSetAttribute(dwpw_wmma,
                         cudaFuncAttributeMaxDynamicSharedMemorySize, GEMM_SMEM_B);

    // A: offsets (512 blocks x 512 threads)
    offset_conv_v5<<<GG * BB * 64, 512, OFFC_SMEM>>>(x, off_w, off_b);

    // Prep: pw hi/lo split (tiny)
    pw_split_kernel<<<(GG * KIN * FG + 255) / 256, 256>>>(pw_w);

    // B: bilinear sampling -> fp16
    long long total_threads = (long long)GG * NPIX * 9 * 32;
    int blocks = (int)(total_threads / 256);
    sample_kernel<<<blocks, 256>>>(x);

    // C: fused depthwise + WMMA pointwise
    dim3 grid(NPIX / 128, GG);
    dwpw_wmma<<<grid, 256, GEMM_SMEM_B>>>(dw_w, dw_b, pw_b, out);
}